// round 12
// baseline (speedup 1.0000x reference)
#include <cuda_runtime.h>
#include <cuda_bf16.h>
#include <stdint.h>
#include <math.h>

#define B_    4
#define C_    192
#define H_    128
#define W_    128
#define HW    16384
#define HEADS 8
#define HD    24
#define C3    576
#define HID   510
#define HID2  1020
#define KPAD  512

// ---------------- scratch (device globals; no allocs) ----------------
__device__ __nv_bfloat16 gb_big[(size_t)B_ * HID2 * HW];
__device__ __nv_bfloat16 gb_qkv[(size_t)B_ * C3 * HW];
__device__ __nv_bfloat16 gb_y  [(size_t)B_ * C_ * HW];
__device__ float g_sumsq[B_ * 2 * C_];
__device__ float g_attn [B_ * HEADS * HD * HD];
__device__ __nv_bfloat16 gw_qkv[640 * 192];
__device__ __nv_bfloat16 gw_in [1024 * 192];
__device__ __nv_bfloat16 gw_out[256 * KPAD];
__device__ __nv_bfloat16 gw_eff[B_ * 256 * 192];   // per-batch folded proj weights

__device__ __forceinline__ unsigned bf2u(__nv_bfloat162 h) { return *(unsigned*)&h; }

// ---------------- prep ----------------
__global__ void prep_kernel(const float* __restrict__ wqkv,
                            const float* __restrict__ win,  const float* __restrict__ wout) {
    const int N1 = 640 * 192, N3 = 1024 * 192, N4 = 256 * KPAD;
    const int N5 = B_ * 2 * C_, N6 = B_ * HEADS * HD * HD;
    const int TOT = N1 + N3 + N4 + N5 + N6;
    for (int i = blockIdx.x * blockDim.x + threadIdx.x; i < TOT; i += gridDim.x * blockDim.x) {
        int j = i;
        if (j < N1) { int m = j / 192, k = j - m * 192;
            gw_qkv[j] = __float2bfloat16(m < C3 ? wqkv[m * 192 + k] : 0.f); continue; }
        j -= N1;
        if (j < N3) { int m = j / 192, k = j - m * 192;
            gw_in[j] = __float2bfloat16(m < HID2 ? win[m * 192 + k] : 0.f); continue; }
        j -= N3;
        if (j < N4) { int m = j / KPAD, k = j - m * KPAD;
            gw_out[j] = __float2bfloat16((m < C_ && k < HID) ? wout[m * HID + k] : 0.f); continue; }
        j -= N4;
        if (j < N5) { g_sumsq[j] = 0.f; continue; }
        j -= N5;
        g_attn[j] = 0.f;
    }
}

// ---------------- channel LayerNorm: fp32 in -> bf16 out (4 pixels/thread) ----------------
__global__ __launch_bounds__(256) void ln_bf_kernel(const float* __restrict__ in,
                                                    const float* __restrict__ w,
                                                    const float* __restrict__ bias,
                                                    __nv_bfloat16* __restrict__ outp) {
    int idx = blockIdx.x * blockDim.x + threadIdx.x;
    int b = idx >> 12;
    int p = (idx & 4095) << 2;
    const float* src = in + (size_t)b * C_ * HW + p;
    float4 s = make_float4(0.f, 0.f, 0.f, 0.f);
    float4 q = make_float4(0.f, 0.f, 0.f, 0.f);
#pragma unroll 8
    for (int c = 0; c < C_; c++) {
        float4 v = *(const float4*)(src + (size_t)c * HW);
        s.x += v.x; s.y += v.y; s.z += v.z; s.w += v.w;
        q.x += v.x * v.x; q.y += v.y * v.y; q.z += v.z * v.z; q.w += v.w * v.w;
    }
    const float ic = 1.0f / C_;
    float4 mu = make_float4(s.x * ic, s.y * ic, s.z * ic, s.w * ic);
    float4 rs;
    rs.x = rsqrtf(q.x * ic - mu.x * mu.x + 1e-5f);
    rs.y = rsqrtf(q.y * ic - mu.y * mu.y + 1e-5f);
    rs.z = rsqrtf(q.z * ic - mu.z * mu.z + 1e-5f);
    rs.w = rsqrtf(q.w * ic - mu.w * mu.w + 1e-5f);
    __nv_bfloat16* dst = outp + (size_t)b * C_ * HW + p;
#pragma unroll 8
    for (int c = 0; c < C_; c++) {
        float4 v = *(const float4*)(src + (size_t)c * HW);
        float wc = w[c], bc = bias[c];
        __nv_bfloat162 h0, h1;
        h0.x = __float2bfloat16((v.x - mu.x) * rs.x * wc + bc);
        h0.y = __float2bfloat16((v.y - mu.y) * rs.y * wc + bc);
        h1.x = __float2bfloat16((v.z - mu.z) * rs.z * wc + bc);
        h1.y = __float2bfloat16((v.w - mu.w) * rs.w * wc + bc);
        uint2 u; u.x = bf2u(h0); u.y = bf2u(h1);
        *(uint2*)(dst + (size_t)c * HW) = u;
    }
}

// ---------------- bf16 tensor-core GEMM (templated K/mode, per-batch A stride) ----------------
#define BM 128
#define BN 128
#define BK 32
#define ASTR 40
#define BSTR 136

__device__ __forceinline__ void cpa16(unsigned dst, const void* src) {
    asm volatile("cp.async.cg.shared.global [%0], [%1], 16;\n" :: "r"(dst), "l"(src));
}

template<int K, int MODE>
__global__ __launch_bounds__(256) void gemm_bf(
    const __nv_bfloat16* __restrict__ A, size_t aStrideB,
    const __nv_bfloat16* __restrict__ Bact, int bStrideCh,
    __nv_bfloat16* __restrict__ OutBf, int outStrideCh,
    float* __restrict__ OutF, const float* __restrict__ Res, int M)
{
    __shared__ __align__(16) __nv_bfloat16 As[2][BM * ASTR];
    __shared__ __align__(16) __nv_bfloat16 Bs[2][BK * BSTR];

    const int b     = blockIdx.z;
    const int nBase = blockIdx.x * BN;
    const int mBase = blockIdx.y * BM;
    const int tid   = threadIdx.x;
    const int lane  = tid & 31, wid = tid >> 5;
    const int warpM = wid >> 2, warpN = wid & 3;
    const int g = lane >> 2, tig = lane & 3;

    const __nv_bfloat16* Ab   = A + (size_t)b * aStrideB;
    const __nv_bfloat16* bsrc = Bact + (size_t)b * bStrideCh * HW;

    float acc[4][4][4];
#pragma unroll
    for (int i = 0; i < 4; i++)
#pragma unroll
        for (int j = 0; j < 4; j++)
#pragma unroll
            for (int r = 0; r < 4; r++) acc[i][j][r] = 0.f;

    constexpr int nIter = K / BK;

    auto load_stage = [&](int s, int k0) {
        unsigned aBase = (unsigned)__cvta_generic_to_shared(&As[s][0]);
        unsigned bBase = (unsigned)__cvta_generic_to_shared(&Bs[s][0]);
#pragma unroll
        for (int u = 0; u < 2; u++) {
            int t  = tid * 2 + u;
            int ar = t >> 2, ac = (t & 3) * 8;
            cpa16(aBase + (unsigned)(ar * ASTR + ac) * 2u,
                  Ab + (size_t)(mBase + ar) * K + k0 + ac);
            int br = t >> 4, bc = (t & 15) * 8;
            cpa16(bBase + (unsigned)(br * BSTR + bc) * 2u,
                  bsrc + (size_t)(k0 + br) * HW + nBase + bc);
        }
    };

    load_stage(0, 0);
    asm volatile("cp.async.commit_group;\n");
    load_stage(1, BK);
    asm volatile("cp.async.commit_group;\n");

    const int aRowSel = ((lane >> 3) & 1) * 8 + (lane & 7);
    const int aKSel   = (lane >> 4) * 8;
    const int bKSel   = ((lane >> 3) & 1) * 8 + (lane & 7);
    const int bNSel   = (lane >> 4) * 8;

#pragma unroll 2
    for (int it = 0; it < nIter; it++) {
        asm volatile("cp.async.wait_group 1;\n");
        __syncthreads();
        const int s = it & 1;
        unsigned aB = (unsigned)__cvta_generic_to_shared(&As[s][0]);
        unsigned bB = (unsigned)__cvta_generic_to_shared(&Bs[s][0]);

#pragma unroll
        for (int ks = 0; ks < 2; ks++) {
            const int kb = ks * 16;
            unsigned af[4][4];
#pragma unroll
            for (int mt = 0; mt < 4; mt++) {
                int mloc = warpM * 64 + mt * 16 + aRowSel;
                unsigned addr = aB + (unsigned)(mloc * ASTR + kb + aKSel) * 2u;
                asm volatile("ldmatrix.sync.aligned.m8n8.x4.shared.b16 {%0,%1,%2,%3}, [%4];"
                             : "=r"(af[mt][0]), "=r"(af[mt][1]), "=r"(af[mt][2]), "=r"(af[mt][3])
                             : "r"(addr));
            }
            unsigned bfr[4][2];
#pragma unroll
            for (int half = 0; half < 2; half++) {
                int kloc = kb + bKSel;
                int nloc = warpN * 32 + half * 16 + bNSel;
                unsigned addr = bB + (unsigned)(kloc * BSTR + nloc) * 2u;
                unsigned r0, r1, r2, r3;
                asm volatile("ldmatrix.sync.aligned.m8n8.x4.trans.shared.b16 {%0,%1,%2,%3}, [%4];"
                             : "=r"(r0), "=r"(r1), "=r"(r2), "=r"(r3) : "r"(addr));
                bfr[half * 2 + 0][0] = r0; bfr[half * 2 + 0][1] = r1;
                bfr[half * 2 + 1][0] = r2; bfr[half * 2 + 1][1] = r3;
            }
#pragma unroll
            for (int mt = 0; mt < 4; mt++)
#pragma unroll
                for (int j = 0; j < 4; j++) {
                    asm volatile(
                        "mma.sync.aligned.m16n8k16.row.col.f32.bf16.bf16.f32 "
                        "{%0,%1,%2,%3}, {%4,%5,%6,%7}, {%8,%9}, {%0,%1,%2,%3};"
                        : "+f"(acc[mt][j][0]), "+f"(acc[mt][j][1]),
                          "+f"(acc[mt][j][2]), "+f"(acc[mt][j][3])
                        : "r"(af[mt][0]), "r"(af[mt][1]), "r"(af[mt][2]), "r"(af[mt][3]),
                          "r"(bfr[j][0]), "r"(bfr[j][1]));
                }
        }
        __syncthreads();
        int knext = (it + 2) * BK;
        if (knext < K) load_stage(s, knext);
        asm volatile("cp.async.commit_group;\n");
    }

#pragma unroll
    for (int mt = 0; mt < 4; mt++) {
        int mLo = mBase + warpM * 64 + mt * 16 + g;
        int mHi = mLo + 8;
#pragma unroll
        for (int j = 0; j < 4; j++) {
            int n = nBase + warpN * 32 + j * 8 + 2 * tig;
            if (MODE == 0) {
                if (mLo < M) {
                    __nv_bfloat162 h;
                    h.x = __float2bfloat16(acc[mt][j][0]);
                    h.y = __float2bfloat16(acc[mt][j][1]);
                    *(__nv_bfloat162*)(OutBf + ((size_t)b * outStrideCh + mLo) * HW + n) = h;
                }
                if (mHi < M) {
                    __nv_bfloat162 h;
                    h.x = __float2bfloat16(acc[mt][j][2]);
                    h.y = __float2bfloat16(acc[mt][j][3]);
                    *(__nv_bfloat162*)(OutBf + ((size_t)b * outStrideCh + mHi) * HW + n) = h;
                }
            } else {
                if (mLo < M) {
                    size_t off = ((size_t)b * M + mLo) * HW + n;
                    float2 v = make_float2(acc[mt][j][0], acc[mt][j][1]);
                    if (MODE == 1) { float2 r = *(const float2*)(Res + off); v.x += r.x; v.y += r.y; }
                    else           { float2 r = *(const float2*)(OutF + off); v.x += r.x; v.y += r.y; }
                    *(float2*)(OutF + off) = v;
                }
                if (mHi < M) {
                    size_t off = ((size_t)b * M + mHi) * HW + n;
                    float2 v = make_float2(acc[mt][j][2], acc[mt][j][3]);
                    if (MODE == 1) { float2 r = *(const float2*)(Res + off); v.x += r.x; v.y += r.y; }
                    else           { float2 r = *(const float2*)(OutF + off); v.x += r.x; v.y += r.y; }
                    *(float2*)(OutF + off) = v;
                }
            }
        }
    }
}

// ---------------- register-direct 3x3 row loader ----------------
__device__ __forceinline__ void load_row10(float* row, const __nv_bfloat16* base,
                                           int y, int c0) {
    if (y >= 0 && y < H_) {
        const __nv_bfloat16* rp = base + y * W_;
        uint4 u = *(const uint4*)(rp + c0);
        __nv_bfloat162* hp = (__nv_bfloat162*)&u;
        float2 f0 = __bfloat1622float2(hp[0]);
        float2 f1 = __bfloat1622float2(hp[1]);
        float2 f2 = __bfloat1622float2(hp[2]);
        float2 f3 = __bfloat1622float2(hp[3]);
        row[1] = f0.x; row[2] = f0.y; row[3] = f1.x; row[4] = f1.y;
        row[5] = f2.x; row[6] = f2.y; row[7] = f3.x; row[8] = f3.y;
        row[0] = (c0 > 0)       ? __bfloat162float(rp[c0 - 1]) : 0.f;
        row[9] = (c0 + 8 < W_)  ? __bfloat162float(rp[c0 + 8]) : 0.f;
    } else {
#pragma unroll
        for (int t = 0; t < 10; t++) row[t] = 0.f;
    }
}

__device__ __forceinline__ float conv_row(const float* r0, const float* r1, const float* r2,
                                          int x, float w0, float w1, float w2, float w3,
                                          float w4, float w5, float w6, float w7, float w8) {
    return w0 * r0[x] + w1 * r0[x + 1] + w2 * r0[x + 2]
         + w3 * r1[x] + w4 * r1[x + 1] + w5 * r1[x + 2]
         + w6 * r2[x] + w7 * r2[x + 1] + w8 * r2[x + 2];
}

// ---------------- depthwise 3x3 qkv: 2 output rows/thread + q/k sumsq ----------------
__global__ __launch_bounds__(256) void dwqkv_kernel(const float* __restrict__ wdw) {
    const int y0 = blockIdx.x * 32, c = blockIdx.y, b = blockIdx.z, tid = threadIdx.x;
    const int r2 = tid >> 4, c0 = (tid & 15) * 8;
    const int y = y0 + r2 * 2;
    const __nv_bfloat16* src = gb_big + ((size_t)b * HID2 + c) * HW;
    float row[4][10];
#pragma unroll
    for (int rr = 0; rr < 4; rr++) load_row10(row[rr], src, y + rr - 1, c0);

    const float* wp = wdw + c * 9;
    const float w0 = wp[0], w1 = wp[1], w2 = wp[2], w3 = wp[3], w4 = wp[4],
                w5 = wp[5], w6 = wp[6], w7 = wp[7], w8 = wp[8];
    float sq = 0.f;
    __nv_bfloat16* dst = gb_qkv + ((size_t)b * C3 + c) * HW;
#pragma unroll
    for (int rr = 0; rr < 2; rr++) {
        __nv_bfloat162 o[4];
#pragma unroll
        for (int x = 0; x < 8; x++) {
            float v = conv_row(row[rr], row[rr + 1], row[rr + 2], x,
                               w0, w1, w2, w3, w4, w5, w6, w7, w8);
            __nv_bfloat16 hb = __float2bfloat16(v);
            float vb = __bfloat162float(hb);
            sq += vb * vb;
            if (x & 1) o[x >> 1].y = hb; else o[x >> 1].x = hb;
        }
        uint4 pack;
        pack.x = bf2u(o[0]); pack.y = bf2u(o[1]); pack.z = bf2u(o[2]); pack.w = bf2u(o[3]);
        *(uint4*)(dst + (y + rr) * W_ + c0) = pack;
    }

    if (c < 2 * C_) {
#pragma unroll
        for (int off = 16; off; off >>= 1) sq += __shfl_xor_sync(0xffffffffu, sq, off);
        __shared__ float ws[8];
        if ((tid & 31) == 0) ws[tid >> 5] = sq;
        __syncthreads();
        if (tid == 0) {
            float t = 0.f;
#pragma unroll
            for (int i = 0; i < 8; i++) t += ws[i];
            atomicAdd(&g_sumsq[b * 2 * C_ + c], t);
        }
    }
}

// ---------------- attention partial scores ----------------
#define PSPLIT 8
__global__ __launch_bounds__(256) void attn_part_kernel() {
    const int ps = blockIdx.x, h = blockIdx.y, b = blockIdx.z;
    const int tid = threadIdx.x, warp = tid >> 5, lane = tid & 31;
    const __nv_bfloat16* base = gb_qkv + (size_t)b * C3 * HW;
    const __nv_bfloat16* qb = base + (size_t)(h * HD) * HW;
    const __nv_bfloat16* kb = base + (size_t)(C_ + h * HD) * HW;
    __shared__ float qs[24][132];
    __shared__ float ks[24][132];

    float acc[3][24];
#pragma unroll
    for (int r = 0; r < 3; r++)
#pragma unroll
        for (int c = 0; c < 24; c++) acc[r][c] = 0.f;

    const int p0 = ps * (HW / PSPLIT);
    for (int t = 0; t < (HW / PSPLIT) / 128; t++) {
        int pt = p0 + t * 128;
        __syncthreads();
        for (int i = tid; i < 768; i += 256) {
            int ch = i >> 5, seg = (i & 31) * 4;
            uint2 u = *(const uint2*)(kb + (size_t)ch * HW + pt + seg);
            float2 f0 = __bfloat1622float2(*(__nv_bfloat162*)&u.x);
            float2 f1 = __bfloat1622float2(*(__nv_bfloat162*)&u.y);
            *(float4*)&ks[ch][seg] = make_float4(f0.x, f0.y, f1.x, f1.y);
            uint2 v = *(const uint2*)(qb + (size_t)ch * HW + pt + seg);
            float2 g0 = __bfloat1622float2(*(__nv_bfloat162*)&v.x);
            float2 g1 = __bfloat1622float2(*(__nv_bfloat162*)&v.y);
            *(float4*)&qs[ch][seg] = make_float4(g0.x, g0.y, g1.x, g1.y);
        }
        __syncthreads();
        float4 qv[3];
#pragma unroll
        for (int r = 0; r < 3; r++)
            qv[r] = *(const float4*)&qs[warp * 3 + r][lane * 4];
#pragma unroll
        for (int ch = 0; ch < 24; ch++) {
            float4 kv = *(const float4*)&ks[ch][lane * 4];
#pragma unroll
            for (int r = 0; r < 3; r++)
                acc[r][ch] += qv[r].x * kv.x + qv[r].y * kv.y + qv[r].z * kv.z + qv[r].w * kv.w;
        }
    }
#pragma unroll
    for (int r = 0; r < 3; r++)
#pragma unroll
        for (int c = 0; c < 24; c++)
#pragma unroll
            for (int off = 16; off; off >>= 1)
                acc[r][c] += __shfl_xor_sync(0xffffffffu, acc[r][c], off);
    if (lane == 0) {
        float* ap = g_attn + (((size_t)(b * HEADS + h)) * HD + warp * 3) * HD;
#pragma unroll
        for (int r = 0; r < 3; r++)
#pragma unroll
            for (int c = 0; c < 24; c++)
                atomicAdd(&ap[r * HD + c], acc[r][c]);
    }
}

// ---------------- softmax finalize ----------------
__global__ void softmax_kernel(const float* __restrict__ temp) {
    int i = blockIdx.x * blockDim.x + threadIdx.x;
    if (i >= B_ * HEADS * HD) return;
    int d = i % HD;
    int bh = i / HD;
    int h = bh % HEADS, b = bh / HEADS;
    float* rowp = g_attn + (size_t)i * HD;
    float sq = g_sumsq[b * 2 * C_ + h * HD + d];
    float rq = 1.0f / fmaxf(sqrtf(sq), 1e-12f);
    float t = temp[h];
    float row[24];
    float mx = -3.4e38f;
#pragma unroll
    for (int c = 0; c < 24; c++) {
        float sk = g_sumsq[b * 2 * C_ + C_ + h * HD + c];
        float rk = 1.0f / fmaxf(sqrtf(sk), 1e-12f);
        row[c] = rowp[c] * rq * rk * t;
        mx = fmaxf(mx, row[c]);
    }
    float sum = 0.f;
#pragma unroll
    for (int c = 0; c < 24; c++) { row[c] = expf(row[c] - mx); sum += row[c]; }
    float inv = 1.0f / sum;
#pragma unroll
    for (int c = 0; c < 24; c++) rowp[c] = row[c] * inv;
}

// ---------------- fold attention into proj weights: Weff[b] = Wproj * blockdiag(A_b) ----
// Weff[b][m][h*24+c] = sum_d Wproj[m][h*24+d] * A[b][h][d][c];  rows padded to 256.
__global__ __launch_bounds__(256) void weff_kernel(const float* __restrict__ wproj) {
    const int b = blockIdx.x;
    __shared__ float As[HEADS * HD * HD];   // 4608 floats
    for (int i = threadIdx.x; i < HEADS * HD * HD; i += 256)
        As[i] = g_attn[(size_t)b * HEADS * HD * HD + i];
    __syncthreads();
    __nv_bfloat16* wd = gw_eff + (size_t)b * 256 * 192;
    for (int i = threadIdx.x; i < 256 * 192; i += 256) {
        int m = i / 192, n = i - m * 192;
        float s = 0.f;
        if (m < C_) {
            int h = n / HD, c = n - h * HD;
            const float* wrow = wproj + m * C_ + h * HD;
            const float* arow = As + (h * HD) * HD + c;
#pragma unroll
            for (int d = 0; d < HD; d++)
                s += wrow[d] * arow[d * HD];
        }
        wd[i] = __float2bfloat16(s);
    }
}

// ---------------- FFN depthwise 3x3 + GELU gate ----------------
__global__ __launch_bounds__(256) void dwgate_kernel(const float* __restrict__ wdw) {
    const int y0 = blockIdx.x * 16, j = blockIdx.y, b = blockIdx.z, tid = threadIdx.x;
    const int r = tid >> 4, c0 = (tid & 15) * 8;
    const int y = y0 + r;
    __nv_bfloat16* dst = gb_qkv + ((size_t)b * C3 + j) * HW;
    if (j >= HID) {
        uint4 z = make_uint4(0u, 0u, 0u, 0u);
        *(uint4*)(dst + y * W_ + c0) = z;
        return;
    }
    const __nv_bfloat16* src1 = gb_big + ((size_t)b * HID2 + j) * HW;
    const __nv_bfloat16* src2 = gb_big + ((size_t)b * HID2 + j + HID) * HW;
    float r1[3][10], r2[3][10];
#pragma unroll
    for (int rr = 0; rr < 3; rr++) {
        load_row10(r1[rr], src1, y + rr - 1, c0);
        load_row10(r2[rr], src2, y + rr - 1, c0);
    }
    const float* wa = wdw + j * 9;
    const float* wb = wdw + (j + HID) * 9;
    const float a0 = wa[0], a1 = wa[1], a2 = wa[2], a3 = wa[3], a4 = wa[4],
                a5 = wa[5], a6 = wa[6], a7 = wa[7], a8 = wa[8];
    const float b0 = wb[0], b1 = wb[1], b2 = wb[2], b3 = wb[3], b4 = wb[4],
                b5 = wb[5], b6 = wb[6], b7 = wb[7], b8 = wb[8];
    __nv_bfloat162 o[4];
#pragma unroll
    for (int x = 0; x < 8; x++) {
        float v1 = conv_row(r1[0], r1[1], r1[2], x, a0, a1, a2, a3, a4, a5, a6, a7, a8);
        float v2 = conv_row(r2[0], r2[1], r2[2], x, b0, b1, b2, b3, b4, b5, b6, b7, b8);
        float gl = 0.5f * v1 * (1.0f + erff(v1 * 0.70710678118654752440f));
        __nv_bfloat16 hb = __float2bfloat16(gl * v2);
        if (x & 1) o[x >> 1].y = hb; else o[x >> 1].x = hb;
    }
    uint4 pack;
    pack.x = bf2u(o[0]); pack.y = bf2u(o[1]); pack.z = bf2u(o[2]); pack.w = bf2u(o[3]);
    *(uint4*)(dst + y * W_ + c0) = pack;
}

// ---------------- launch ----------------
extern "C" void kernel_launch(void* const* d_in, const int* in_sizes, int n_in,
                              void* d_out, int out_size) {
    const float* x      = (const float*)d_in[0];
    const float* temp   = (const float*)d_in[1];
    const float* ln1w   = (const float*)d_in[2];
    const float* ln1b   = (const float*)d_in[3];
    const float* ln2w   = (const float*)d_in[4];
    const float* ln2b   = (const float*)d_in[5];
    const float* wqkv   = (const float*)d_in[6];
    const float* wqkvdw = (const float*)d_in[7];
    const float* wproj  = (const float*)d_in[8];
    const float* win    = (const float*)d_in[9];
    const float* wdw    = (const float*)d_in[10];
    const float* wout   = (const float*)d_in[11];
    float* out = (float*)d_out;

    __nv_bfloat16 *pBig, *pQkv, *pY, *pWqkv, *pWin, *pWout, *pWeff;
    cudaGetSymbolAddress((void**)&pBig,  gb_big);
    cudaGetSymbolAddress((void**)&pQkv,  gb_qkv);
    cudaGetSymbolAddress((void**)&pY,    gb_y);
    cudaGetSymbolAddress((void**)&pWqkv, gw_qkv);
    cudaGetSymbolAddress((void**)&pWin,  gw_in);
    cudaGetSymbolAddress((void**)&pWout, gw_out);
    cudaGetSymbolAddress((void**)&pWeff, gw_eff);

    prep_kernel<<<512, 256>>>(wqkv, win, wout);

    // --- attention branch ---
    ln_bf_kernel<<<(B_ * HW / 4) / 256, 256>>>(x, ln1w, ln1b, pY);
    gemm_bf<192, 0><<<dim3(128, 5, B_), 256>>>(pWqkv, 0, pY, C_, pBig, HID2, nullptr, nullptr, C3);
    dwqkv_kernel<<<dim3(4, C3, B_), 256>>>(wqkvdw);
    attn_part_kernel<<<dim3(PSPLIT, HEADS, B_), 256>>>();
    softmax_kernel<<<3, 256>>>(temp);
    weff_kernel<<<B_, 256>>>(wproj);
    // proj folded with attention: out = Weff[b] @ V + x   (V = channels 2C..3C of gb_qkv)
    gemm_bf<192, 1><<<dim3(128, 2, B_), 256>>>(pWeff, (size_t)256 * 192,
        pQkv + (size_t)2 * C_ * HW, C3, nullptr, 0, out, x, C_);

    // --- FFN branch ---
    ln_bf_kernel<<<(B_ * HW / 4) / 256, 256>>>(out, ln2w, ln2b, pY);
    gemm_bf<192, 0><<<dim3(128, 8, B_), 256>>>(pWin, 0, pY, C_, pBig, HID2, nullptr, nullptr, HID2);
    dwgate_kernel<<<dim3(8, KPAD, B_), 256>>>(wdw);
    gemm_bf<512, 2><<<dim3(128, 2, B_), 256>>>(pWout, 0, pQkv, C3, nullptr, 0, out, nullptr, C_);
}

// round 15
// speedup vs baseline: 1.1112x; 1.1112x over previous
#include <cuda_runtime.h>
#include <cuda_bf16.h>
#include <stdint.h>
#include <math.h>

#define B_    4
#define C_    192
#define H_    128
#define W_    128
#define HW    16384
#define HEADS 8
#define HD    24
#define C3    576
#define HID   510
#define HID2  1020
#define KPAD  512

// ---------------- scratch (device globals; no allocs) ----------------
__device__ __nv_bfloat16 gb_big[(size_t)B_ * HID2 * HW];
__device__ __nv_bfloat16 gb_qkv[(size_t)B_ * C3 * HW];
__device__ __nv_bfloat16 gb_y  [(size_t)B_ * C_ * HW];
__device__ float g_sumsq[B_ * 2 * C_];
__device__ float g_attn [B_ * HEADS * HD * HD];
__device__ __nv_bfloat16 gw_qkv[640 * 192];
__device__ __nv_bfloat16 gw_proj[256 * 192];
__device__ __nv_bfloat16 gw_in [1024 * 192];
__device__ __nv_bfloat16 gw_out[256 * KPAD];

__device__ __forceinline__ unsigned bf2u(__nv_bfloat162 h) { return *(unsigned*)&h; }

// ---------------- prep ----------------
__global__ void prep_kernel(const float* __restrict__ wqkv, const float* __restrict__ wproj,
                            const float* __restrict__ win,  const float* __restrict__ wout) {
    const int N1 = 640 * 192, N2 = 256 * 192, N3 = 1024 * 192, N4 = 256 * KPAD;
    const int N5 = B_ * 2 * C_, N6 = B_ * HEADS * HD * HD;
    const int TOT = N1 + N2 + N3 + N4 + N5 + N6;
    for (int i = blockIdx.x * blockDim.x + threadIdx.x; i < TOT; i += gridDim.x * blockDim.x) {
        int j = i;
        if (j < N1) { int m = j / 192, k = j - m * 192;
            gw_qkv[j] = __float2bfloat16(m < C3 ? wqkv[m * 192 + k] : 0.f); continue; }
        j -= N1;
        if (j < N2) { int m = j / 192, k = j - m * 192;
            gw_proj[j] = __float2bfloat16(m < C_ ? wproj[m * 192 + k] : 0.f); continue; }
        j -= N2;
        if (j < N3) { int m = j / 192, k = j - m * 192;
            gw_in[j] = __float2bfloat16(m < HID2 ? win[m * 192 + k] : 0.f); continue; }
        j -= N3;
        if (j < N4) { int m = j / KPAD, k = j - m * KPAD;
            gw_out[j] = __float2bfloat16((m < C_ && k < HID) ? wout[m * HID + k] : 0.f); continue; }
        j -= N4;
        if (j < N5) { g_sumsq[j] = 0.f; continue; }
        j -= N5;
        g_attn[j] = 0.f;
    }
}

// ---------------- channel LayerNorm: fp32 in -> bf16 out (4 pixels/thread) ----------------
__global__ __launch_bounds__(256) void ln_bf_kernel(const float* __restrict__ in,
                                                    const float* __restrict__ w,
                                                    const float* __restrict__ bias,
                                                    __nv_bfloat16* __restrict__ outp) {
    int idx = blockIdx.x * blockDim.x + threadIdx.x;
    int b = idx >> 12;
    int p = (idx & 4095) << 2;
    const float* src = in + (size_t)b * C_ * HW + p;
    float4 s = make_float4(0.f, 0.f, 0.f, 0.f);
    float4 q = make_float4(0.f, 0.f, 0.f, 0.f);
#pragma unroll 8
    for (int c = 0; c < C_; c++) {
        float4 v = *(const float4*)(src + (size_t)c * HW);
        s.x += v.x; s.y += v.y; s.z += v.z; s.w += v.w;
        q.x += v.x * v.x; q.y += v.y * v.y; q.z += v.z * v.z; q.w += v.w * v.w;
    }
    const float ic = 1.0f / C_;
    float4 mu = make_float4(s.x * ic, s.y * ic, s.z * ic, s.w * ic);
    float4 rs;
    rs.x = rsqrtf(q.x * ic - mu.x * mu.x + 1e-5f);
    rs.y = rsqrtf(q.y * ic - mu.y * mu.y + 1e-5f);
    rs.z = rsqrtf(q.z * ic - mu.z * mu.z + 1e-5f);
    rs.w = rsqrtf(q.w * ic - mu.w * mu.w + 1e-5f);
    __nv_bfloat16* dst = outp + (size_t)b * C_ * HW + p;
#pragma unroll 8
    for (int c = 0; c < C_; c++) {
        float4 v = *(const float4*)(src + (size_t)c * HW);
        float wc = w[c], bc = bias[c];
        __nv_bfloat162 h0, h1;
        h0.x = __float2bfloat16((v.x - mu.x) * rs.x * wc + bc);
        h0.y = __float2bfloat16((v.y - mu.y) * rs.y * wc + bc);
        h1.x = __float2bfloat16((v.z - mu.z) * rs.z * wc + bc);
        h1.y = __float2bfloat16((v.w - mu.w) * rs.w * wc + bc);
        uint2 u; u.x = bf2u(h0); u.y = bf2u(h1);
        *(uint2*)(dst + (size_t)c * HW) = u;
    }
}

// ---------------- bf16 tensor-core GEMM (templated K/mode) ----------------
#define BM 128
#define BN 128
#define BK 32
#define ASTR 40
#define BSTR 136

__device__ __forceinline__ void cpa16(unsigned dst, const void* src) {
    asm volatile("cp.async.cg.shared.global [%0], [%1], 16;\n" :: "r"(dst), "l"(src));
}

template<int K, int MODE>
__global__ __launch_bounds__(256) void gemm_bf(
    const __nv_bfloat16* __restrict__ A,
    const __nv_bfloat16* __restrict__ Bact, int bStrideCh,
    __nv_bfloat16* __restrict__ OutBf, int outStrideCh,
    float* __restrict__ OutF, const float* __restrict__ Res, int M)
{
    __shared__ __align__(16) __nv_bfloat16 As[2][BM * ASTR];
    __shared__ __align__(16) __nv_bfloat16 Bs[2][BK * BSTR];

    const int b     = blockIdx.z;
    const int nBase = blockIdx.x * BN;
    const int mBase = blockIdx.y * BM;
    const int tid   = threadIdx.x;
    const int lane  = tid & 31, wid = tid >> 5;
    const int warpM = wid >> 2, warpN = wid & 3;
    const int g = lane >> 2, tig = lane & 3;

    const __nv_bfloat16* bsrc = Bact + (size_t)b * bStrideCh * HW;

    float acc[4][4][4];
#pragma unroll
    for (int i = 0; i < 4; i++)
#pragma unroll
        for (int j = 0; j < 4; j++)
#pragma unroll
            for (int r = 0; r < 4; r++) acc[i][j][r] = 0.f;

    constexpr int nIter = K / BK;

    auto load_stage = [&](int s, int k0) {
        unsigned aBase = (unsigned)__cvta_generic_to_shared(&As[s][0]);
        unsigned bBase = (unsigned)__cvta_generic_to_shared(&Bs[s][0]);
#pragma unroll
        for (int u = 0; u < 2; u++) {
            int t  = tid * 2 + u;
            int ar = t >> 2, ac = (t & 3) * 8;
            cpa16(aBase + (unsigned)(ar * ASTR + ac) * 2u,
                  A + (size_t)(mBase + ar) * K + k0 + ac);
            int br = t >> 4, bc = (t & 15) * 8;
            cpa16(bBase + (unsigned)(br * BSTR + bc) * 2u,
                  bsrc + (size_t)(k0 + br) * HW + nBase + bc);
        }
    };

    load_stage(0, 0);
    asm volatile("cp.async.commit_group;\n");
    load_stage(1, BK);
    asm volatile("cp.async.commit_group;\n");

    const int aRowSel = ((lane >> 3) & 1) * 8 + (lane & 7);
    const int aKSel   = (lane >> 4) * 8;
    const int bKSel   = ((lane >> 3) & 1) * 8 + (lane & 7);
    const int bNSel   = (lane >> 4) * 8;

#pragma unroll 2
    for (int it = 0; it < nIter; it++) {
        asm volatile("cp.async.wait_group 1;\n");
        __syncthreads();
        const int s = it & 1;
        unsigned aB = (unsigned)__cvta_generic_to_shared(&As[s][0]);
        unsigned bB = (unsigned)__cvta_generic_to_shared(&Bs[s][0]);

#pragma unroll
        for (int ks = 0; ks < 2; ks++) {
            const int kb = ks * 16;
            unsigned af[4][4];
#pragma unroll
            for (int mt = 0; mt < 4; mt++) {
                int mloc = warpM * 64 + mt * 16 + aRowSel;
                unsigned addr = aB + (unsigned)(mloc * ASTR + kb + aKSel) * 2u;
                asm volatile("ldmatrix.sync.aligned.m8n8.x4.shared.b16 {%0,%1,%2,%3}, [%4];"
                             : "=r"(af[mt][0]), "=r"(af[mt][1]), "=r"(af[mt][2]), "=r"(af[mt][3])
                             : "r"(addr));
            }
            unsigned bfr[4][2];
#pragma unroll
            for (int half = 0; half < 2; half++) {
                int kloc = kb + bKSel;
                int nloc = warpN * 32 + half * 16 + bNSel;
                unsigned addr = bB + (unsigned)(kloc * BSTR + nloc) * 2u;
                unsigned r0, r1, r2, r3;
                asm volatile("ldmatrix.sync.aligned.m8n8.x4.trans.shared.b16 {%0,%1,%2,%3}, [%4];"
                             : "=r"(r0), "=r"(r1), "=r"(r2), "=r"(r3) : "r"(addr));
                bfr[half * 2 + 0][0] = r0; bfr[half * 2 + 0][1] = r1;
                bfr[half * 2 + 1][0] = r2; bfr[half * 2 + 1][1] = r3;
            }
#pragma unroll
            for (int mt = 0; mt < 4; mt++)
#pragma unroll
                for (int j = 0; j < 4; j++) {
                    asm volatile(
                        "mma.sync.aligned.m16n8k16.row.col.f32.bf16.bf16.f32 "
                        "{%0,%1,%2,%3}, {%4,%5,%6,%7}, {%8,%9}, {%0,%1,%2,%3};"
                        : "+f"(acc[mt][j][0]), "+f"(acc[mt][j][1]),
                          "+f"(acc[mt][j][2]), "+f"(acc[mt][j][3])
                        : "r"(af[mt][0]), "r"(af[mt][1]), "r"(af[mt][2]), "r"(af[mt][3]),
                          "r"(bfr[j][0]), "r"(bfr[j][1]));
                }
        }
        __syncthreads();
        int knext = (it + 2) * BK;
        if (knext < K) load_stage(s, knext);
        asm volatile("cp.async.commit_group;\n");
    }

#pragma unroll
    for (int mt = 0; mt < 4; mt++) {
        int mLo = mBase + warpM * 64 + mt * 16 + g;
        int mHi = mLo + 8;
#pragma unroll
        for (int j = 0; j < 4; j++) {
            int n = nBase + warpN * 32 + j * 8 + 2 * tig;
            if (MODE == 0) {
                if (mLo < M) {
                    __nv_bfloat162 h;
                    h.x = __float2bfloat16(acc[mt][j][0]);
                    h.y = __float2bfloat16(acc[mt][j][1]);
                    *(__nv_bfloat162*)(OutBf + ((size_t)b * outStrideCh + mLo) * HW + n) = h;
                }
                if (mHi < M) {
                    __nv_bfloat162 h;
                    h.x = __float2bfloat16(acc[mt][j][2]);
                    h.y = __float2bfloat16(acc[mt][j][3]);
                    *(__nv_bfloat162*)(OutBf + ((size_t)b * outStrideCh + mHi) * HW + n) = h;
                }
            } else {
                if (mLo < M) {
                    size_t off = ((size_t)b * M + mLo) * HW + n;
                    float2 v = make_float2(acc[mt][j][0], acc[mt][j][1]);
                    if (MODE == 1) { float2 r = *(const float2*)(Res + off); v.x += r.x; v.y += r.y; }
                    else           { float2 r = *(const float2*)(OutF + off); v.x += r.x; v.y += r.y; }
                    *(float2*)(OutF + off) = v;
                }
                if (mHi < M) {
                    size_t off = ((size_t)b * M + mHi) * HW + n;
                    float2 v = make_float2(acc[mt][j][2], acc[mt][j][3]);
                    if (MODE == 1) { float2 r = *(const float2*)(Res + off); v.x += r.x; v.y += r.y; }
                    else           { float2 r = *(const float2*)(OutF + off); v.x += r.x; v.y += r.y; }
                    *(float2*)(OutF + off) = v;
                }
            }
        }
    }
}

// ---------------- register-direct 3x3 row loader ----------------
__device__ __forceinline__ void load_row10(float* row, const __nv_bfloat16* base,
                                           int y, int c0) {
    if (y >= 0 && y < H_) {
        const __nv_bfloat16* rp = base + y * W_;
        uint4 u = *(const uint4*)(rp + c0);
        __nv_bfloat162* hp = (__nv_bfloat162*)&u;
        float2 f0 = __bfloat1622float2(hp[0]);
        float2 f1 = __bfloat1622float2(hp[1]);
        float2 f2 = __bfloat1622float2(hp[2]);
        float2 f3 = __bfloat1622float2(hp[3]);
        row[1] = f0.x; row[2] = f0.y; row[3] = f1.x; row[4] = f1.y;
        row[5] = f2.x; row[6] = f2.y; row[7] = f3.x; row[8] = f3.y;
        row[0] = (c0 > 0)       ? __bfloat162float(rp[c0 - 1]) : 0.f;
        row[9] = (c0 + 8 < W_)  ? __bfloat162float(rp[c0 + 8]) : 0.f;
    } else {
#pragma unroll
        for (int t = 0; t < 10; t++) row[t] = 0.f;
    }
}

__device__ __forceinline__ float conv_row(const float* r0, const float* r1, const float* r2,
                                          int x, float w0, float w1, float w2, float w3,
                                          float w4, float w5, float w6, float w7, float w8) {
    return w0 * r0[x] + w1 * r0[x + 1] + w2 * r0[x + 2]
         + w3 * r1[x] + w4 * r1[x + 1] + w5 * r1[x + 2]
         + w6 * r2[x] + w7 * r2[x + 1] + w8 * r2[x + 2];
}

// ---------------- depthwise 3x3 qkv: 2 output rows/thread + q/k sumsq ----------------
__global__ __launch_bounds__(256) void dwqkv_kernel(const float* __restrict__ wdw) {
    const int y0 = blockIdx.x * 32, c = blockIdx.y, b = blockIdx.z, tid = threadIdx.x;
    const int r2 = tid >> 4, c0 = (tid & 15) * 8;
    const int y = y0 + r2 * 2;
    const __nv_bfloat16* src = gb_big + ((size_t)b * HID2 + c) * HW;
    float row[4][10];
#pragma unroll
    for (int rr = 0; rr < 4; rr++) load_row10(row[rr], src, y + rr - 1, c0);

    const float* wp = wdw + c * 9;
    const float w0 = wp[0], w1 = wp[1], w2 = wp[2], w3 = wp[3], w4 = wp[4],
                w5 = wp[5], w6 = wp[6], w7 = wp[7], w8 = wp[8];
    float sq = 0.f;
    __nv_bfloat16* dst = gb_qkv + ((size_t)b * C3 + c) * HW;
#pragma unroll
    for (int rr = 0; rr < 2; rr++) {
        __nv_bfloat162 o[4];
#pragma unroll
        for (int x = 0; x < 8; x++) {
            float v = conv_row(row[rr], row[rr + 1], row[rr + 2], x,
                               w0, w1, w2, w3, w4, w5, w6, w7, w8);
            __nv_bfloat16 hb = __float2bfloat16(v);
            float vb = __bfloat162float(hb);
            sq += vb * vb;
            if (x & 1) o[x >> 1].y = hb; else o[x >> 1].x = hb;
        }
        uint4 pack;
        pack.x = bf2u(o[0]); pack.y = bf2u(o[1]); pack.z = bf2u(o[2]); pack.w = bf2u(o[3]);
        *(uint4*)(dst + (y + rr) * W_ + c0) = pack;
    }

    if (c < 2 * C_) {
#pragma unroll
        for (int off = 16; off; off >>= 1) sq += __shfl_xor_sync(0xffffffffu, sq, off);
        __shared__ float ws[8];
        if ((tid & 31) == 0) ws[tid >> 5] = sq;
        __syncthreads();
        if (tid == 0) {
            float t = 0.f;
#pragma unroll
            for (int i = 0; i < 8; i++) t += ws[i];
            atomicAdd(&g_sumsq[b * 2 * C_ + c], t);
        }
    }
}

// ---------------- attention partial scores ----------------
#define PSPLIT 8
__global__ __launch_bounds__(256) void attn_part_kernel() {
    const int ps = blockIdx.x, h = blockIdx.y, b = blockIdx.z;
    const int tid = threadIdx.x, warp = tid >> 5, lane = tid & 31;
    const __nv_bfloat16* base = gb_qkv + (size_t)b * C3 * HW;
    const __nv_bfloat16* qb = base + (size_t)(h * HD) * HW;
    const __nv_bfloat16* kb = base + (size_t)(C_ + h * HD) * HW;
    __shared__ float qs[24][132];
    __shared__ float ks[24][132];

    float acc[3][24];
#pragma unroll
    for (int r = 0; r < 3; r++)
#pragma unroll
        for (int c = 0; c < 24; c++) acc[r][c] = 0.f;

    const int p0 = ps * (HW / PSPLIT);
    for (int t = 0; t < (HW / PSPLIT) / 128; t++) {
        int pt = p0 + t * 128;
        __syncthreads();
        for (int i = tid; i < 768; i += 256) {
            int ch = i >> 5, seg = (i & 31) * 4;
            uint2 u = *(const uint2*)(kb + (size_t)ch * HW + pt + seg);
            float2 f0 = __bfloat1622float2(*(__nv_bfloat162*)&u.x);
            float2 f1 = __bfloat1622float2(*(__nv_bfloat162*)&u.y);
            *(float4*)&ks[ch][seg] = make_float4(f0.x, f0.y, f1.x, f1.y);
            uint2 v = *(const uint2*)(qb + (size_t)ch * HW + pt + seg);
            float2 g0 = __bfloat1622float2(*(__nv_bfloat162*)&v.x);
            float2 g1 = __bfloat1622float2(*(__nv_bfloat162*)&v.y);
            *(float4*)&qs[ch][seg] = make_float4(g0.x, g0.y, g1.x, g1.y);
        }
        __syncthreads();
        float4 qv[3];
#pragma unroll
        for (int r = 0; r < 3; r++)
            qv[r] = *(const float4*)&qs[warp * 3 + r][lane * 4];
#pragma unroll
        for (int ch = 0; ch < 24; ch++) {
            float4 kv = *(const float4*)&ks[ch][lane * 4];
#pragma unroll
            for (int r = 0; r < 3; r++)
                acc[r][ch] += qv[r].x * kv.x + qv[r].y * kv.y + qv[r].z * kv.z + qv[r].w * kv.w;
        }
    }
#pragma unroll
    for (int r = 0; r < 3; r++)
#pragma unroll
        for (int c = 0; c < 24; c++)
#pragma unroll
            for (int off = 16; off; off >>= 1)
                acc[r][c] += __shfl_xor_sync(0xffffffffu, acc[r][c], off);
    if (lane == 0) {
        float* ap = g_attn + (((size_t)(b * HEADS + h)) * HD + warp * 3) * HD;
#pragma unroll
        for (int r = 0; r < 3; r++)
#pragma unroll
            for (int c = 0; c < 24; c++)
                atomicAdd(&ap[r * HD + c], acc[r][c]);
    }
}

// ---------------- softmax finalize ----------------
__global__ void softmax_kernel(const float* __restrict__ temp) {
    int i = blockIdx.x * blockDim.x + threadIdx.x;
    if (i >= B_ * HEADS * HD) return;
    int d = i % HD;
    int bh = i / HD;
    int h = bh % HEADS, b = bh / HEADS;
    float* rowp = g_attn + (size_t)i * HD;
    float sq = g_sumsq[b * 2 * C_ + h * HD + d];
    float rq = 1.0f / fmaxf(sqrtf(sq), 1e-12f);
    float t = temp[h];
    float row[24];
    float mx = -3.4e38f;
#pragma unroll
    for (int c = 0; c < 24; c++) {
        float sk = g_sumsq[b * 2 * C_ + C_ + h * HD + c];
        float rk = 1.0f / fmaxf(sqrtf(sk), 1e-12f);
        row[c] = rowp[c] * rq * rk * t;
        mx = fmaxf(mx, row[c]);
    }
    float sum = 0.f;
#pragma unroll
    for (int c = 0; c < 24; c++) { row[c] = expf(row[c] - mx); sum += row[c]; }
    float inv = 1.0f / sum;
#pragma unroll
    for (int c = 0; c < 24; c++) rowp[c] = row[c] * inv;
}

// ---------------- out = attn @ v -> gb_y (bf16), 4 pixels/thread ----------------
__global__ __launch_bounds__(256) void av_kernel() {
    int tid = threadIdx.x;
    int p = blockIdx.x * 1024 + tid * 4;
    int h = blockIdx.y, b = blockIdx.z;
    __shared__ float A[HD * HD];
    const float* ap = g_attn + ((size_t)(b * HEADS + h)) * HD * HD;
    for (int i = tid; i < HD * HD; i += 256) A[i] = ap[i];
    __syncthreads();
    const __nv_bfloat16* vb = gb_qkv + (size_t)b * C3 * HW + (size_t)(2 * C_ + h * HD) * HW;
    float4 v[24];
#pragma unroll
    for (int c = 0; c < 24; c++) {
        uint2 u = *(const uint2*)(vb + (size_t)c * HW + p);
        float2 f0 = __bfloat1622float2(*(__nv_bfloat162*)&u.x);
        float2 f1 = __bfloat1622float2(*(__nv_bfloat162*)&u.y);
        v[c] = make_float4(f0.x, f0.y, f1.x, f1.y);
    }
    __nv_bfloat16* ob = gb_y + (size_t)b * C_ * HW + (size_t)(h * HD) * HW;
#pragma unroll
    for (int d = 0; d < 24; d++) {
        float s0 = 0.f, s1 = 0.f, s2 = 0.f, s3 = 0.f;
#pragma unroll
        for (int c = 0; c < 24; c++) {
            float a = A[d * 24 + c];
            s0 += a * v[c].x; s1 += a * v[c].y; s2 += a * v[c].z; s3 += a * v[c].w;
        }
        __nv_bfloat162 h0, h1;
        h0.x = __float2bfloat16(s0); h0.y = __float2bfloat16(s1);
        h1.x = __float2bfloat16(s2); h1.y = __float2bfloat16(s3);
        uint2 u; u.x = bf2u(h0); u.y = bf2u(h1);
        *(uint2*)(ob + (size_t)d * HW + p) = u;
    }
}

// ---------------- FFN depthwise 3x3 + GELU gate ----------------
__global__ __launch_bounds__(256) void dwgate_kernel(const float* __restrict__ wdw) {
    const int y0 = blockIdx.x * 16, j = blockIdx.y, b = blockIdx.z, tid = threadIdx.x;
    const int r = tid >> 4, c0 = (tid & 15) * 8;
    const int y = y0 + r;
    __nv_bfloat16* dst = gb_qkv + ((size_t)b * C3 + j) * HW;
    if (j >= HID) {
        uint4 z = make_uint4(0u, 0u, 0u, 0u);
        *(uint4*)(dst + y * W_ + c0) = z;
        return;
    }
    const __nv_bfloat16* src1 = gb_big + ((size_t)b * HID2 + j) * HW;
    const __nv_bfloat16* src2 = gb_big + ((size_t)b * HID2 + j + HID) * HW;
    float r1[3][10], r2[3][10];
#pragma unroll
    for (int rr = 0; rr < 3; rr++) {
        load_row10(r1[rr], src1, y + rr - 1, c0);
        load_row10(r2[rr], src2, y + rr - 1, c0);
    }
    const float* wa = wdw + j * 9;
    const float* wb = wdw + (j + HID) * 9;
    const float a0 = wa[0], a1 = wa[1], a2 = wa[2], a3 = wa[3], a4 = wa[4],
                a5 = wa[5], a6 = wa[6], a7 = wa[7], a8 = wa[8];
    const float b0 = wb[0], b1 = wb[1], b2 = wb[2], b3 = wb[3], b4 = wb[4],
                b5 = wb[5], b6 = wb[6], b7 = wb[7], b8 = wb[8];
    __nv_bfloat162 o[4];
#pragma unroll
    for (int x = 0; x < 8; x++) {
        float v1 = conv_row(r1[0], r1[1], r1[2], x, a0, a1, a2, a3, a4, a5, a6, a7, a8);
        float v2 = conv_row(r2[0], r2[1], r2[2], x, b0, b1, b2, b3, b4, b5, b6, b7, b8);
        float gl = 0.5f * v1 * (1.0f + erff(v1 * 0.70710678118654752440f));
        __nv_bfloat16 hb = __float2bfloat16(gl * v2);
        if (x & 1) o[x >> 1].y = hb; else o[x >> 1].x = hb;
    }
    uint4 pack;
    pack.x = bf2u(o[0]); pack.y = bf2u(o[1]); pack.z = bf2u(o[2]); pack.w = bf2u(o[3]);
    *(uint4*)(dst + y * W_ + c0) = pack;
}

// ---------------- launch ----------------
extern "C" void kernel_launch(void* const* d_in, const int* in_sizes, int n_in,
                              void* d_out, int out_size) {
    const float* x      = (const float*)d_in[0];
    const float* temp   = (const float*)d_in[1];
    const float* ln1w   = (const float*)d_in[2];
    const float* ln1b   = (const float*)d_in[3];
    const float* ln2w   = (const float*)d_in[4];
    const float* ln2b   = (const float*)d_in[5];
    const float* wqkv   = (const float*)d_in[6];
    const float* wqkvdw = (const float*)d_in[7];
    const float* wproj  = (const float*)d_in[8];
    const float* win    = (const float*)d_in[9];
    const float* wdw    = (const float*)d_in[10];
    const float* wout   = (const float*)d_in[11];
    float* out = (float*)d_out;

    __nv_bfloat16 *pBig, *pQkv, *pY, *pWqkv, *pWproj, *pWin, *pWout;
    cudaGetSymbolAddress((void**)&pBig,  gb_big);
    cudaGetSymbolAddress((void**)&pQkv,  gb_qkv);
    cudaGetSymbolAddress((void**)&pY,    gb_y);
    cudaGetSymbolAddress((void**)&pWqkv, gw_qkv);
    cudaGetSymbolAddress((void**)&pWproj,gw_proj);
    cudaGetSymbolAddress((void**)&pWin,  gw_in);
    cudaGetSymbolAddress((void**)&pWout, gw_out);

    prep_kernel<<<512, 256>>>(wqkv, wproj, win, wout);

    // --- attention branch ---
    ln_bf_kernel<<<(B_ * HW / 4) / 256, 256>>>(x, ln1w, ln1b, pY);
    gemm_bf<192, 0><<<dim3(128, 5, B_), 256>>>(pWqkv, pY, C_, pBig, HID2, nullptr, nullptr, C3);
    dwqkv_kernel<<<dim3(4, C3, B_), 256>>>(wqkvdw);
    attn_part_kernel<<<dim3(PSPLIT, HEADS, B_), 256>>>();
    softmax_kernel<<<3, 256>>>(temp);
    av_kernel<<<dim3(HW / 1024, HEADS, B_), 256>>>();
    gemm_bf<192, 1><<<dim3(128, 2, B_), 256>>>(pWproj, pY, C_, nullptr, 0, out, x, C_);

    // --- FFN branch ---
    ln_bf_kernel<<<(B_ * HW / 4) / 256, 256>>>(out, ln2w, ln2b, pY);
    gemm_bf<192, 0><<<dim3(128, 8, B_), 256>>>(pWin, pY, C_, pBig, HID2, nullptr, nullptr, HID2);
    dwgate_kernel<<<dim3(8, KPAD, B_), 256>>>(wdw);
    gemm_bf<512, 2><<<dim3(128, 2, B_), 256>>>(pWout, pQkv, C3, nullptr, 0, out, nullptr, C_);
}